// round 9
// baseline (speedup 1.0000x reference)
#include <cuda_runtime.h>
#include <cstdint>

#define B_   16
#define TE_  128
#define TD_  64
#define H_   256
#define OUT_ 32000

// ---------------- scratch (static device array; no runtime alloc) ----------------
// enc_gi   2048*768   @ 0
// dec_gi   1024*768   @ 1,572,864
// enc_out  2048*256   @ 2,359,296
// enc_hT   16*256     @ 2,883,584
// cat      1024*512   @ 2,887,680   (cols 0:256 dec_out, 256:512 context)
// Penc     2048*256   @ 3,411,968
// Pdec     1024*256   @ 3,936,256
// dense    1024*256   @ 4,198,400
__device__ float g_scratch[4460544];

// ---------------- fast math ----------------
__device__ __forceinline__ float fsig(float x) {
    return __fdividef(1.f, 1.f + __expf(-x));
}
__device__ __forceinline__ float ftanh(float x) {
    float e = __expf(2.f * x);                 // inf for big x -> 1; 0 for very neg -> -1
    return 1.f - __fdividef(2.f, e + 1.f);
}
__device__ __forceinline__ uint32_t su32(const void* p) {
    uint32_t a;
    asm("{ .reg .u64 t; cvta.to.shared.u64 t, %1; cvt.u32.u64 %0, t; }" : "=r"(a) : "l"(p));
    return a;
}

// ---------------- tiled SGEMM: C[m,n] = act( sum_k A[m,k]*B[n,k] + bias[n] ) ----------
// BM=BN=128, BK=16, 256 threads, 8x8 microtile. M,N multiples of 128; K multiple of 16.
// Optional row-gather on A (embedding lookup).
template <int ACT>
__global__ void __launch_bounds__(256)
gemm_kernel(int M, int N, int K,
            const float* __restrict__ A, int lda, const int* __restrict__ gather,
            const float* __restrict__ Bm, int ldb, int boff,
            const float* __restrict__ bias,
            float* __restrict__ C, int ldc)
{
    __shared__ float As[16][128];
    __shared__ float Bs[16][128];
    const int bm = blockIdx.y * 128, bn = blockIdx.x * 128;
    const int tid = threadIdx.x;
    const int tx = tid & 15, ty = tid >> 4;

    const float* aptr[2];
    const float* bptr[2];
#pragma unroll
    for (int it = 0; it < 2; it++) {
        int idx = tid + it * 256;             // 0..511
        int row = idx >> 2, k4 = idx & 3;
        int ar = bm + row;
        long g = gather ? (long)gather[ar] : (long)ar;
        aptr[it] = A + g * (long)lda + k4 * 4;
        bptr[it] = Bm + (long)(bn + row) * ldb + boff + k4 * 4;
    }

    float acc[8][8];
#pragma unroll
    for (int i = 0; i < 8; i++)
#pragma unroll
        for (int j = 0; j < 8; j++) acc[i][j] = 0.f;

    for (int k0 = 0; k0 < K; k0 += 16) {
#pragma unroll
        for (int it = 0; it < 2; it++) {
            int idx = tid + it * 256;
            int row = idx >> 2, k4 = idx & 3;
            float4 va = *(const float4*)(aptr[it] + k0);
            As[k4 * 4 + 0][row] = va.x; As[k4 * 4 + 1][row] = va.y;
            As[k4 * 4 + 2][row] = va.z; As[k4 * 4 + 3][row] = va.w;
            float4 vb = *(const float4*)(bptr[it] + k0);
            Bs[k4 * 4 + 0][row] = vb.x; Bs[k4 * 4 + 1][row] = vb.y;
            Bs[k4 * 4 + 2][row] = vb.z; Bs[k4 * 4 + 3][row] = vb.w;
        }
        __syncthreads();
#pragma unroll
        for (int k = 0; k < 16; k++) {
            float a[8], b[8];
            *(float4*)&a[0] = *(const float4*)&As[k][ty * 8];
            *(float4*)&a[4] = *(const float4*)&As[k][ty * 8 + 4];
            *(float4*)&b[0] = *(const float4*)&Bs[k][tx * 8];
            *(float4*)&b[4] = *(const float4*)&Bs[k][tx * 8 + 4];
#pragma unroll
            for (int i = 0; i < 8; i++)
#pragma unroll
                for (int j = 0; j < 8; j++) acc[i][j] += a[i] * b[j];
        }
        __syncthreads();
    }

    float bv[8];
#pragma unroll
    for (int j = 0; j < 8; j++) bv[j] = bias ? bias[bn + tx * 8 + j] : 0.f;
#pragma unroll
    for (int i = 0; i < 8; i++) {
        long m = bm + ty * 8 + i;
        float o[8];
#pragma unroll
        for (int j = 0; j < 8; j++) {
            float v = acc[i][j] + bv[j];
            if (ACT) v = ftanh(v);
            o[j] = v;
        }
        *(float4*)(C + m * (long)ldc + bn + tx * 8)     = *(float4*)&o[0];
        *(float4*)(C + m * (long)ldc + bn + tx * 8 + 4) = *(float4*)&o[4];
    }
}

// ---------------- persistent GRU: one cluster of 8 CTAs per batch element --------------
// CTA c owns hidden units [c*32, c*32+32): Whh rows {g*256 + c*32 + i}. Whh slice in SMEM
// (rows padded to 260 floats -> conflict-free float4 reads; h reads are broadcast).
// h double-buffered; new values broadcast to all 8 CTAs via st.shared::cluster, ordered
// by barrier.cluster (release/acquire).
__global__ void __launch_bounds__(128) __cluster_dims__(8, 1, 1)
gru_kernel(const float* __restrict__ gi, const float* __restrict__ Whh,
           const float* __restrict__ bhh, const int* __restrict__ lengths,
           const float* __restrict__ h0, float* __restrict__ outp, int ostride,
           float* __restrict__ hT, int T)
{
    extern __shared__ float sm[];
    float* Wsh  = sm;                 // 96*260
    float* hb0  = sm + 96 * 260;      // 256
    float* hb1  = hb0 + 256;          // 256
    float* gh_s = hb1 + 256;          // 96
    float* bg_s = gh_s + 96;          // 96

    const int c = blockIdx.x;         // == cluster rank (grid.x == cluster.x == 8)
    const int b = blockIdx.y;
    const int tid = threadIdx.x;
    const int len = lengths[b];

    for (int i = tid; i < 96 * 256; i += 128) {
        int r = i >> 8, k = i & 255;
        int grow = (r >> 5) * 256 + c * 32 + (r & 31);
        Wsh[r * 260 + k] = Whh[grow * 256 + k];
    }
    if (tid < 96) {
        int grow = (tid >> 5) * 256 + c * 32 + (tid & 31);
        bg_s[tid] = bhh[grow];
    }
    for (int j = tid; j < 256; j += 128)
        hb0[j] = h0 ? h0[b * 256 + j] : 0.f;

    asm volatile("barrier.cluster.arrive.aligned;\n" ::: "memory");
    asm volatile("barrier.cluster.wait.aligned;\n" ::: "memory");

    for (int t = 0; t < T; t++) {
        float* hcur = (t & 1) ? hb1 : hb0;
        float* hnxt = (t & 1) ? hb0 : hb1;

        if (tid < 96) {
            const float4* wr = (const float4*)(Wsh + tid * 260);
            const float4* hp = (const float4*)hcur;
            float a0 = 0.f, a1 = 0.f, a2 = 0.f, a3 = 0.f;
#pragma unroll
            for (int k = 0; k < 64; k++) {
                float4 w = wr[k]; float4 h4 = hp[k];
                a0 += w.x * h4.x; a1 += w.y * h4.y;
                a2 += w.z * h4.z; a3 += w.w * h4.w;
            }
            gh_s[tid] = (a0 + a1) + (a2 + a3) + bg_s[tid];
        }
        __syncthreads();

        if (tid < 32) {
            int idx = c * 32 + tid;
            long base = ((long)(b * T + t)) * 768;
            float rg = fsig(gi[base + idx]        + gh_s[tid]);
            float zg = fsig(gi[base + 256 + idx]  + gh_s[32 + tid]);
            float ng = ftanh(gi[base + 512 + idx] + rg * gh_s[64 + tid]);
            float hold = hcur[idx];
            float hnew = (1.f - zg) * ng + zg * hold;
            bool valid = (t < len);
            float hsel = valid ? hnew : hold;
            outp[((long)(b * T + t)) * ostride + idx] = valid ? hnew : 0.f;

            uint32_t laddr = su32(&hnxt[idx]);
#pragma unroll
            for (int tc = 0; tc < 8; tc++) {
                uint32_t raddr;
                asm volatile("mapa.shared::cluster.u32 %0, %1, %2;"
                             : "=r"(raddr) : "r"(laddr), "r"(tc));
                asm volatile("st.shared::cluster.f32 [%0], %1;"
                             :: "r"(raddr), "f"(hsel) : "memory");
            }
        }
        asm volatile("barrier.cluster.arrive.aligned;\n" ::: "memory");
        asm volatile("barrier.cluster.wait.aligned;\n" ::: "memory");
    }

    if (hT && tid < 32) {
        float* hfin = (T & 1) ? hb1 : hb0;
        int idx = c * 32 + tid;
        hT[b * 256 + idx] = hfin[idx];
    }
}

// ---------------- fused attention: energies -> softmax(valid) -> context ----------------
// (unmasked softmax -> mask -> renormalize) == softmax over valid encoder steps.
__global__ void __launch_bounds__(256)
attn_kernel(const float* __restrict__ Penc, const float* __restrict__ Pdec,
            const float* __restrict__ enc_out, const float* __restrict__ av,
            const float* __restrict__ avb, const int* __restrict__ elen_p,
            const int* __restrict__ dlen_p, float* __restrict__ cat)
{
    const int b = blockIdx.y, td = blockIdx.x;
    const int tid = threadIdx.x;
    const long row = (long)b * TD_ + td;

    if (td >= dlen_p[b]) {            // fully masked decoder step: context = 0
        cat[row * 512 + 256 + tid] = 0.f;
        return;
    }
    __shared__ float Pd_s[256], v_s[256], e_s[128], red_s[16];
    Pd_s[tid] = Pdec[row * 256 + tid];
    v_s[tid]  = av[tid];
    const int elen = elen_p[b];
    const float vb = avb[0];
    __syncthreads();

    const int warp = tid >> 5, lane = tid & 31;
    for (int te = warp; te < elen; te += 8) {
        const float* pe = Penc + ((long)b * TE_ + te) * 256;
        float s = 0.f;
#pragma unroll
        for (int j = 0; j < 8; j++) {
            int h = lane + j * 32;
            s += ftanh(pe[h] + Pd_s[h]) * v_s[h];
        }
#pragma unroll
        for (int o = 16; o; o >>= 1) s += __shfl_xor_sync(0xffffffffu, s, o);
        if (lane == 0) e_s[te] = s + vb;
    }
    __syncthreads();

    float x = (tid < elen) ? e_s[tid] : -1e30f;
    float m = x;
#pragma unroll
    for (int o = 16; o; o >>= 1) m = fmaxf(m, __shfl_xor_sync(0xffffffffu, m, o));
    if (lane == 0) red_s[warp] = m;
    __syncthreads();
    float mx = red_s[0];
#pragma unroll
    for (int i = 1; i < 8; i++) mx = fmaxf(mx, red_s[i]);

    float p = (tid < elen) ? __expf(x - mx) : 0.f;
    float ps = p;
#pragma unroll
    for (int o = 16; o; o >>= 1) ps += __shfl_xor_sync(0xffffffffu, ps, o);
    if (lane == 0) red_s[8 + warp] = ps;
    __syncthreads();
    float sum = 0.f;
#pragma unroll
    for (int i = 0; i < 8; i++) sum += red_s[8 + i];
    float inv = __fdividef(1.f, sum);
    if (tid < 128) e_s[tid] = p * inv;
    __syncthreads();

    float acc = 0.f;
    const float* eo = enc_out + ((long)b * TE_) * 256 + tid;   // tid = h
    int te = 0;
    for (; te + 4 <= elen; te += 4) {
        acc += e_s[te]     * eo[(long)te * 256];
        acc += e_s[te + 1] * eo[(long)(te + 1) * 256];
        acc += e_s[te + 2] * eo[(long)(te + 2) * 256];
        acc += e_s[te + 3] * eo[(long)(te + 3) * 256];
    }
    for (; te < elen; te++) acc += e_s[te] * eo[(long)te * 256];
    cat[row * 512 + 256 + tid] = acc;
}

// ---------------- launch ----------------
extern "C" void kernel_launch(void* const* d_in, const int* in_sizes, int n_in,
                              void* d_out, int out_size)
{
    (void)in_sizes; (void)n_in; (void)out_size;
    const int*   enc_in  = (const int*)d_in[0];
    const int*   enc_len = (const int*)d_in[1];
    const int*   dec_in  = (const int*)d_in[2];
    const int*   dec_len = (const int*)d_in[3];
    const float* emb     = (const float*)d_in[4];
    const float* eWih = (const float*)d_in[5];
    const float* eWhh = (const float*)d_in[6];
    const float* ebih = (const float*)d_in[7];
    const float* ebhh = (const float*)d_in[8];
    const float* dWih = (const float*)d_in[9];
    const float* dWhh = (const float*)d_in[10];
    const float* dbih = (const float*)d_in[11];
    const float* dbhh = (const float*)d_in[12];
    const float* aW   = (const float*)d_in[13];
    const float* aWb  = (const float*)d_in[14];
    const float* av   = (const float*)d_in[15];
    const float* avb  = (const float*)d_in[16];
    const float* dnW  = (const float*)d_in[17];
    const float* dnb  = (const float*)d_in[18];
    const float* oW   = (const float*)d_in[19];
    const float* ob   = (const float*)d_in[20];
    float* out = (float*)d_out;

    float* S = nullptr;
    cudaGetSymbolAddress((void**)&S, g_scratch);
    float* enc_gi  = S;
    float* dec_gi  = S + 1572864;
    float* enc_out = S + 2359296;
    float* enc_hT  = S + 2883584;
    float* cat     = S + 2887680;
    float* Penc    = S + 3411968;
    float* Pdec    = S + 3936256;
    float* dense   = S + 4198400;

    const size_t gru_smem = (96 * 260 + 256 + 256 + 96 + 96) * sizeof(float); // ~102.7 KB
    cudaFuncSetAttribute(gru_kernel, cudaFuncAttributeMaxDynamicSharedMemorySize,
                         (int)gru_smem);

    // gi pre-GEMMs (embedding gather fused)
    gemm_kernel<0><<<dim3(6, 16), 256>>>(2048, 768, 256, emb, 256, enc_in,
                                         eWih, 256, 0, ebih, enc_gi, 768);
    gemm_kernel<0><<<dim3(6, 8), 256>>>(1024, 768, 256, emb, 256, dec_in,
                                        dWih, 256, 0, dbih, dec_gi, 768);

    // encoder GRU (persistent, 16 clusters x 8 CTAs)
    gru_kernel<<<dim3(8, 16), 128, gru_smem>>>(enc_gi, eWhh, ebhh, enc_len,
                                               nullptr, enc_out, 256, enc_hT, TE_);

    // Penc = enc_out @ attn_W[:, :256]^T
    gemm_kernel<0><<<dim3(2, 16), 256>>>(2048, 256, 256, enc_out, 256, nullptr,
                                         aW, 512, 0, nullptr, Penc, 256);

    // decoder GRU -> cat[:, 0:256]
    gru_kernel<<<dim3(8, 16), 128, gru_smem>>>(dec_gi, dWhh, dbhh, dec_len,
                                               enc_hT, cat, 512, nullptr, TD_);

    // Pdec = dec_out @ attn_W[:, 256:512]^T + attn_Wb
    gemm_kernel<0><<<dim3(2, 8), 256>>>(1024, 256, 256, cat, 512, nullptr,
                                        aW, 512, 256, aWb, Pdec, 256);

    // fused attention -> cat[:, 256:512]
    attn_kernel<<<dim3(TD_, B_), 256>>>(Penc, Pdec, enc_out, av, avb,
                                        enc_len, dec_len, cat);

    // dense = tanh(cat @ dense_W^T + dense_b)
    gemm_kernel<1><<<dim3(2, 8), 256>>>(1024, 256, 512, cat, 512, nullptr,
                                        dnW, 512, 0, dnb, dense, 256);

    // logits = dense @ out_W^T + out_b  (dominant GEMM)
    gemm_kernel<0><<<dim3(250, 8), 256>>>(1024, 32000, 256, dense, 256, nullptr,
                                          oW, 256, 0, ob, out, 32000);
}